// round 1
// baseline (speedup 1.0000x reference)
#include <cuda_runtime.h>

#define ADAPTERS  40
#define CAPS      3
#define CLASS_DIM 200
#define IN_CH     600
#define BATCH     256
#define DOUT      768

// ---------------- scratch (device globals; no allocation allowed) ------------
__device__ float  g_priors[(size_t)CAPS * BATCH * ADAPTERS * CLASS_DIM]; // 24.6 MB
__device__ float  g_vote[(size_t)CAPS * BATCH * CLASS_DIM];              // (n,b,d) flat
__device__ float4 g_gw[DOUT];                                            // {g*w0,g*w1,g*w2,g*b}

// ---------------- Stage A: priors[n,b,k,d] = sum_c x[b,k,c]*rw[k,n,c,d] -----
// 64x64 output tile per block, KC=16, 16x16 threads, 4x4 microtile.
// Blocks with k > t exit immediately (their probs are exactly 0 downstream).
__global__ void priors_kernel(const int* __restrict__ t_ptr,
                              const float* __restrict__ x,
                              const float* __restrict__ rw) {
    const int k = blockIdx.y;
    const int n = blockIdx.z;
    if (k > *t_ptr) return;

    const int bt = blockIdx.x & 3;   // 4 b-tiles (256/64)
    const int dt = blockIdx.x >> 2;  // 4 d-tiles (ceil(200/64))
    const int b0 = bt * 64;
    const int d0 = dt * 64;

    __shared__ float As[16][65];   // [cc][row]
    __shared__ float Bs[16][64];   // [cc][col]

    const int tid = threadIdx.x;
    const int tx  = tid & 15;
    const int ty  = tid >> 4;

    float acc[4][4] = {};

    const float* xk = x  + (size_t)k * IN_CH;
    const float* wk = rw + ((size_t)(k * CAPS + n)) * IN_CH * CLASS_DIM;

    for (int c0 = 0; c0 < IN_CH; c0 += 16) {
        #pragma unroll
        for (int i = tid; i < 64 * 16; i += 256) {
            int cc = i & 15, rr = i >> 4;
            int c  = c0 + cc;
            As[cc][rr] = (c < IN_CH)
                ? xk[(size_t)(b0 + rr) * (ADAPTERS * IN_CH) + c] : 0.f;
        }
        #pragma unroll
        for (int i = tid; i < 64 * 16; i += 256) {
            int dd = i & 63, cc = i >> 6;
            int c  = c0 + cc, d = d0 + dd;
            Bs[cc][dd] = (c < IN_CH && d < CLASS_DIM)
                ? wk[(size_t)c * CLASS_DIM + d] : 0.f;
        }
        __syncthreads();

        #pragma unroll
        for (int cc = 0; cc < 16; cc++) {
            float a[4], b[4];
            #pragma unroll
            for (int u = 0; u < 4; u++) a[u] = As[cc][ty + 16 * u];
            #pragma unroll
            for (int v = 0; v < 4; v++) b[v] = Bs[cc][tx + 16 * v];
            #pragma unroll
            for (int u = 0; u < 4; u++)
                #pragma unroll
                for (int v = 0; v < 4; v++)
                    acc[u][v] += a[u] * b[v];
        }
        __syncthreads();
    }

    #pragma unroll
    for (int u = 0; u < 4; u++) {
        int b = b0 + ty + 16 * u;
        #pragma unroll
        for (int v = 0; v < 4; v++) {
            int d = d0 + tx + 16 * v;
            if (d < CLASS_DIM)
                g_priors[(((size_t)n * BATCH + b) * ADAPTERS + k) * CLASS_DIM + d]
                    = acc[u][v];
        }
    }
}

// ---------------- Stage B: dynamic routing (3 iterations) --------------------
// One block per (b, n). Priors for k<=t live in shared memory.
__global__ void routing_kernel(const int* __restrict__ t_ptr,
                               const float* __restrict__ tsv) {
    const int b   = blockIdx.x;
    const int n   = blockIdx.y;
    const int t   = *t_ptr;
    const int nk  = t + 1;
    const int tid = threadIdx.x;

    __shared__ float sp[ADAPTERS][CLASS_DIM]; // 32 KB
    __shared__ float sout[CLASS_DIM];
    __shared__ float sL[ADAPTERS];
    __shared__ float sprob[ADAPTERS];
    __shared__ float stw[ADAPTERS];
    __shared__ float red[256];

    const float* pbase = g_priors + (((size_t)n * BATCH + b) * ADAPTERS) * CLASS_DIM;
    for (int i = tid; i < nk * CLASS_DIM; i += 256)
        sp[i / CLASS_DIM][i % CLASS_DIM] = pbase[i];

    if (tid < ADAPTERS) {
        sL[tid]  = 0.f;
        stw[tid] = tsv[t * ADAPTERS + tid];
    }
    __syncthreads();

    for (int it = 0; it < 3; it++) {
        if (tid == 0) {
            float mx = -1e30f;
            for (int k = 0; k < nk; k++) {
                float tw = stw[k];
                float L  = sL[k] * tw + (tw == 0.f ? -10000.f : 0.f);
                sL[k] = L;
                mx = fmaxf(mx, L);
            }
            float sum = 0.f;
            for (int k = 0; k < nk; k++) {
                float e = expf(sL[k] - mx);
                sprob[k] = e;
                sum += e;
            }
            float inv = 1.f / sum;
            for (int k = 0; k < nk; k++) sprob[k] *= inv;
        }
        __syncthreads();

        float v = 0.f;
        if (tid < CLASS_DIM)
            for (int k = 0; k < nk; k++) v += sprob[k] * sp[k][tid];

        red[tid] = (tid < CLASS_DIM) ? v * v : 0.f;
        __syncthreads();
        for (int s = 128; s > 0; s >>= 1) {
            if (tid < s) red[tid] += red[tid + s];
            __syncthreads();
        }
        float sq = red[0];

        if (it == 2) {
            if (tid < CLASS_DIM)
                g_vote[((size_t)n * BATCH + b) * CLASS_DIM + tid] = v;
        } else {
            float scale = sq / (1.f + sq) * rsqrtf(sq);
            if (tid < CLASS_DIM) sout[tid] = v * scale;
            __syncthreads();
            // delta_k = dot_d(priors[k,:], out); one warp per k
            int wid = tid >> 5, lane = tid & 31;
            for (int k = wid; k < nk; k += 8) {
                float p = 0.f;
                for (int d = lane; d < CLASS_DIM; d += 32) p += sp[k][d] * sout[d];
                #pragma unroll
                for (int off = 16; off; off >>= 1)
                    p += __shfl_down_sync(0xffffffffu, p, off);
                if (lane == 0) sL[k] += p;
            }
            __syncthreads();
        }
    }
}

// ---------------- Stage pre-C: fold gate into weights ------------------------
__global__ void gw_kernel(const int* __restrict__ t_ptr,
                          const float* __restrict__ s,
                          const float* __restrict__ lw,
                          const float* __restrict__ lb,
                          const float* __restrict__ elarger) {
    int j = blockIdx.x * 256 + threadIdx.x;
    if (j >= DOUT) return;
    int t = *t_ptr;
    float g = 1.f / (1.f + expf(-s[0] * elarger[t * DOUT + j]));
    float4 w;
    w.x = g * lw[j * 3 + 0];
    w.y = g * lw[j * 3 + 1];
    w.z = g * lw[j * 3 + 2];
    w.w = g * lb[j];
    g_gw[j] = w;
}

// ---------------- Stage C: out[row, j] = sum_c h_c * gw[j].c + gw[j].w -------
// row = b2*200+d2; h_c = g_vote[row*3+c] (the reshape preserves flat order).
// 192 threads = 768 outputs/row as float4; 8 rows per block to reuse gw regs.
__global__ void out_kernel(float* __restrict__ out) {
    const int tid = threadIdx.x;       // 0..191
    float4 w[4];
    #pragma unroll
    for (int q = 0; q < 4; q++) w[q] = g_gw[tid * 4 + q];

    size_t row = (size_t)blockIdx.x * 8;
    #pragma unroll
    for (int r = 0; r < 8; r++, row++) {
        float v0 = g_vote[row * 3 + 0];
        float v1 = g_vote[row * 3 + 1];
        float v2 = g_vote[row * 3 + 2];
        float4 res;
        res.x = v0 * w[0].x + v1 * w[0].y + v2 * w[0].z + w[0].w;
        res.y = v0 * w[1].x + v1 * w[1].y + v2 * w[1].z + w[1].w;
        res.z = v0 * w[2].x + v1 * w[2].y + v2 * w[2].z + w[2].w;
        res.w = v0 * w[3].x + v1 * w[3].y + v2 * w[3].z + w[3].w;
        ((float4*)(out + row * DOUT))[tid] = res;
    }
}

// ---------------- launch -----------------------------------------------------
extern "C" void kernel_launch(void* const* d_in, const int* in_sizes, int n_in,
                              void* d_out, int out_size) {
    const int*   t_ptr   = (const int*)  d_in[0];
    const float* x       = (const float*)d_in[1];
    const float* s       = (const float*)d_in[2];
    const float* rw      = (const float*)d_in[3];
    const float* lw      = (const float*)d_in[4];
    const float* lb      = (const float*)d_in[5];
    const float* elarger = (const float*)d_in[6];
    const float* tsv     = (const float*)d_in[7];
    float* out = (float*)d_out;

    priors_kernel<<<dim3(16, ADAPTERS, CAPS), 256>>>(t_ptr, x, rw);
    routing_kernel<<<dim3(BATCH, CAPS), 256>>>(t_ptr, tsv);
    gw_kernel<<<3, 256>>>(t_ptr, s, lw, lb, elarger);
    out_kernel<<<(BATCH * CLASS_DIM) / 8, 192>>>(out);
}

// round 4
// speedup vs baseline: 1.0069x; 1.0069x over previous
#include <cuda_runtime.h>
#include <cuda_bf16.h>
#include <mma.h>
using namespace nvcuda;

#define ADAPTERS  40
#define CAPS      3
#define CLASS_DIM 200
#define IN_CH     600
#define BATCH     256
#define DOUT      768
#define PDIM      256                 // padded class dim for maskless wmma stores
#define PSTR      (ADAPTERS * PDIM)

// ---------------- scratch (device globals; no allocation allowed) ------------
__device__ float  g_priors[(size_t)CAPS * BATCH * ADAPTERS * PDIM]; // 31.5 MB
__device__ float  g_vote[(size_t)CAPS * BATCH * CLASS_DIM];
__device__ float4 g_gw[DOUT];

// 3-way bf16 split: v = b1 + b2 + b3 + O(2^-24 |v|).
// bf16 x bf16 products are EXACT in fp32, so HMMA.BF16+fp32-acc loses nothing
// in the product datapath (unlike sm_103a HMMA.TF32, which rounds products).
__device__ __forceinline__ void split3(float v, __nv_bfloat16& b1,
                                       __nv_bfloat16& b2, __nv_bfloat16& b3) {
    b1 = __float2bfloat16(v);
    float r1 = v - __bfloat162float(b1);
    b2 = __float2bfloat16(r1);
    float r2 = r1 - __bfloat162float(b2);
    b3 = __float2bfloat16(r2);
}

// ---------------- Stage A: priors[n,b,k,d] = sum_c x[b,k,c]*rw[k,n,c,d] -----
// bf16 tensor GEMM, 6-term split emulation of fp32.
// Block tile 128x64, BK=32, 8 warps (4x2), warp tile 32x32 (2x2 m16n16k16).
#define BM 128
#define BN 64
#define BK 32
#define LDA 40
#define LDB 72

__global__ void priors_kernel(const int* __restrict__ t_ptr,
                              const float* __restrict__ x,
                              const float* __restrict__ rw) {
    const int k = blockIdx.y;
    const int n = blockIdx.z;
    if (k > *t_ptr) return;           // exactly-zero softmax weight downstream

    const int bt = blockIdx.x & 1;    // 2 b-tiles
    const int dt = blockIdx.x >> 1;   // 4 d-tiles (cover padded 256)
    const int b0 = bt * BM;
    const int d0 = dt * BN;

    __shared__ __nv_bfloat16 As1[BM * LDA], As2[BM * LDA], As3[BM * LDA];
    __shared__ __nv_bfloat16 Bs1[BK * LDB], Bs2[BK * LDB], Bs3[BK * LDB];

    const int tid = threadIdx.x;
    const int wid = tid >> 5;
    const int wr  = wid & 3;          // warp row (4)
    const int wc  = wid >> 2;         // warp col (2)

    wmma::fragment<wmma::accumulator, 16, 16, 16, float> acc[2][2];
    #pragma unroll
    for (int i = 0; i < 2; i++)
        #pragma unroll
        for (int j = 0; j < 2; j++) wmma::fill_fragment(acc[i][j], 0.f);

    const float* xk = x  + (size_t)k * IN_CH;
    const float* wk = rw + ((size_t)(k * CAPS + n)) * IN_CH * CLASS_DIM;

    for (int c0 = 0; c0 < IN_CH; c0 += BK) {
        // A tile: 128 rows x 32 c
        #pragma unroll
        for (int i = tid; i < BM * 8; i += 256) {
            int row = i >> 3, c4 = (i & 7) * 4;
            float4 v = make_float4(0.f, 0.f, 0.f, 0.f);
            if (c0 + c4 < IN_CH)
                v = *(const float4*)&xk[(size_t)(b0 + row) * (ADAPTERS * IN_CH) + c0 + c4];
            __nv_bfloat16 h[4], m[4], l[4];
            split3(v.x, h[0], m[0], l[0]);
            split3(v.y, h[1], m[1], l[1]);
            split3(v.z, h[2], m[2], l[2]);
            split3(v.w, h[3], m[3], l[3]);
            int off = row * LDA + c4;
            *(__nv_bfloat162*)&As1[off]     = __nv_bfloat162(h[0], h[1]);
            *(__nv_bfloat162*)&As1[off + 2] = __nv_bfloat162(h[2], h[3]);
            *(__nv_bfloat162*)&As2[off]     = __nv_bfloat162(m[0], m[1]);
            *(__nv_bfloat162*)&As2[off + 2] = __nv_bfloat162(m[2], m[3]);
            *(__nv_bfloat162*)&As3[off]     = __nv_bfloat162(l[0], l[1]);
            *(__nv_bfloat162*)&As3[off + 2] = __nv_bfloat162(l[2], l[3]);
        }
        // B tile: 32 c x 64 d
        #pragma unroll
        for (int i = tid; i < BK * 16; i += 256) {
            int row = i >> 4, d4 = (i & 15) * 4;
            float4 v = make_float4(0.f, 0.f, 0.f, 0.f);
            int c = c0 + row, d = d0 + d4;
            if (c < IN_CH && d < CLASS_DIM)
                v = *(const float4*)&wk[(size_t)c * CLASS_DIM + d];
            __nv_bfloat16 h[4], m[4], l[4];
            split3(v.x, h[0], m[0], l[0]);
            split3(v.y, h[1], m[1], l[1]);
            split3(v.z, h[2], m[2], l[2]);
            split3(v.w, h[3], m[3], l[3]);
            int off = row * LDB + d4;
            *(__nv_bfloat162*)&Bs1[off]     = __nv_bfloat162(h[0], h[1]);
            *(__nv_bfloat162*)&Bs1[off + 2] = __nv_bfloat162(h[2], h[3]);
            *(__nv_bfloat162*)&Bs2[off]     = __nv_bfloat162(m[0], m[1]);
            *(__nv_bfloat162*)&Bs2[off + 2] = __nv_bfloat162(m[2], m[3]);
            *(__nv_bfloat162*)&Bs3[off]     = __nv_bfloat162(l[0], l[1]);
            *(__nv_bfloat162*)&Bs3[off + 2] = __nv_bfloat162(l[2], l[3]);
        }
        __syncthreads();

        #pragma unroll
        for (int ks = 0; ks < 2; ks++) {
            wmma::fragment<wmma::matrix_a, 16, 16, 16, __nv_bfloat16, wmma::row_major> a1[2], a2[2], a3[2];
            wmma::fragment<wmma::matrix_b, 16, 16, 16, __nv_bfloat16, wmma::row_major> b1[2], b2[2], b3[2];
            #pragma unroll
            for (int i = 0; i < 2; i++) {
                int aoff = (wr * 32 + i * 16) * LDA + ks * 16;
                wmma::load_matrix_sync(a1[i], &As1[aoff], LDA);
                wmma::load_matrix_sync(a2[i], &As2[aoff], LDA);
                wmma::load_matrix_sync(a3[i], &As3[aoff], LDA);
            }
            #pragma unroll
            for (int j = 0; j < 2; j++) {
                int boff = (ks * 16) * LDB + wc * 32 + j * 16;
                wmma::load_matrix_sync(b1[j], &Bs1[boff], LDB);
                wmma::load_matrix_sync(b2[j], &Bs2[boff], LDB);
                wmma::load_matrix_sync(b3[j], &Bs3[boff], LDB);
            }
            #pragma unroll
            for (int i = 0; i < 2; i++)
                #pragma unroll
                for (int j = 0; j < 2; j++) {
                    // smallest-magnitude terms first
                    wmma::mma_sync(acc[i][j], a2[i], b2[j], acc[i][j]);
                    wmma::mma_sync(acc[i][j], a3[i], b1[j], acc[i][j]);
                    wmma::mma_sync(acc[i][j], a1[i], b3[j], acc[i][j]);
                    wmma::mma_sync(acc[i][j], a2[i], b1[j], acc[i][j]);
                    wmma::mma_sync(acc[i][j], a1[i], b2[j], acc[i][j]);
                    wmma::mma_sync(acc[i][j], a1[i], b1[j], acc[i][j]);
                }
        }
        __syncthreads();
    }

    float* gp = g_priors + (((size_t)n * BATCH + b0 + wr * 32) * ADAPTERS + k) * PDIM
              + d0 + wc * 32;
    #pragma unroll
    for (int i = 0; i < 2; i++)
        #pragma unroll
        for (int j = 0; j < 2; j++)
            wmma::store_matrix_sync(gp + (size_t)i * 16 * PSTR + j * 16,
                                    acc[i][j], PSTR, wmma::mem_row_major);
}

// ---------------- Stage B: dynamic routing (3 iterations) --------------------
__global__ void routing_kernel(const int* __restrict__ t_ptr,
                               const float* __restrict__ tsv) {
    const int b   = blockIdx.x;
    const int n   = blockIdx.y;
    const int t   = *t_ptr;
    const int nk  = t + 1;
    const int tid = threadIdx.x;

    __shared__ float sp[ADAPTERS][CLASS_DIM]; // 32 KB
    __shared__ float sout[CLASS_DIM];
    __shared__ float sL[ADAPTERS];
    __shared__ float sprob[ADAPTERS];
    __shared__ float stw[ADAPTERS];
    __shared__ float red[256];

    const float* pbase = g_priors + (((size_t)n * BATCH + b) * ADAPTERS) * PDIM;
    for (int i = tid; i < nk * CLASS_DIM; i += 256) {
        int kk = i / CLASS_DIM, d = i % CLASS_DIM;
        sp[kk][d] = pbase[(size_t)kk * PDIM + d];
    }

    if (tid < ADAPTERS) {
        sL[tid]  = 0.f;
        stw[tid] = tsv[t * ADAPTERS + tid];
    }
    __syncthreads();

    for (int it = 0; it < 3; it++) {
        if (tid == 0) {
            float mx = -1e30f;
            for (int kk = 0; kk < nk; kk++) {
                float tw = stw[kk];
                float L  = sL[kk] * tw + (tw == 0.f ? -10000.f : 0.f);
                sL[kk] = L;
                mx = fmaxf(mx, L);
            }
            float sum = 0.f;
            for (int kk = 0; kk < nk; kk++) {
                float e = expf(sL[kk] - mx);
                sprob[kk] = e;
                sum += e;
            }
            float inv = 1.f / sum;
            for (int kk = 0; kk < nk; kk++) sprob[kk] *= inv;
        }
        __syncthreads();

        float v = 0.f;
        if (tid < CLASS_DIM)
            for (int kk = 0; kk < nk; kk++) v += sprob[kk] * sp[kk][tid];

        red[tid] = (tid < CLASS_DIM) ? v * v : 0.f;
        __syncthreads();
        for (int s = 128; s > 0; s >>= 1) {
            if (tid < s) red[tid] += red[tid + s];
            __syncthreads();
        }
        float sq = red[0];

        if (it == 2) {
            if (tid < CLASS_DIM)
                g_vote[((size_t)n * BATCH + b) * CLASS_DIM + tid] = v;
        } else {
            float scale = sq / (1.f + sq) * rsqrtf(sq);
            if (tid < CLASS_DIM) sout[tid] = v * scale;
            __syncthreads();
            int wid = tid >> 5, lane = tid & 31;
            for (int kk = wid; kk < nk; kk += 8) {
                float p = 0.f;
                for (int d = lane; d < CLASS_DIM; d += 32) p += sp[kk][d] * sout[d];
                #pragma unroll
                for (int off = 16; off; off >>= 1)
                    p += __shfl_down_sync(0xffffffffu, p, off);
                if (lane == 0) sL[kk] += p;
            }
            __syncthreads();
        }
    }
}

// ---------------- Stage pre-C: fold gate into weights ------------------------
__global__ void gw_kernel(const int* __restrict__ t_ptr,
                          const float* __restrict__ s,
                          const float* __restrict__ lw,
                          const float* __restrict__ lb,
                          const float* __restrict__ elarger) {
    int j = blockIdx.x * 256 + threadIdx.x;
    if (j >= DOUT) return;
    int t = *t_ptr;
    float g = 1.f / (1.f + expf(-s[0] * elarger[t * DOUT + j]));
    float4 w;
    w.x = g * lw[j * 3 + 0];
    w.y = g * lw[j * 3 + 1];
    w.z = g * lw[j * 3 + 2];
    w.w = g * lb[j];
    g_gw[j] = w;
}

// ---------------- Stage C: out[row, j] = sum_c h_c * gw[j].c + gw[j].w -------
__global__ void out_kernel(float* __restrict__ out) {
    const int tid = threadIdx.x;       // 0..191
    float4 w[4];
    #pragma unroll
    for (int q = 0; q < 4; q++) w[q] = g_gw[tid * 4 + q];

    size_t row = (size_t)blockIdx.x * 8;
    #pragma unroll
    for (int r = 0; r < 8; r++, row++) {
        float v0 = g_vote[row * 3 + 0];
        float v1 = g_vote[row * 3 + 1];
        float v2 = g_vote[row * 3 + 2];
        float4 res;
        res.x = v0 * w[0].x + v1 * w[0].y + v2 * w[0].z + w[0].w;
        res.y = v0 * w[1].x + v1 * w[1].y + v2 * w[1].z + w[1].w;
        res.z = v0 * w[2].x + v1 * w[2].y + v2 * w[2].z + w[2].w;
        res.w = v0 * w[3].x + v1 * w[3].y + v2 * w[3].z + w[3].w;
        __stcs(((float4*)(out + row * DOUT)) + tid, res);
    }
}

// ---------------- launch -----------------------------------------------------
extern "C" void kernel_launch(void* const* d_in, const int* in_sizes, int n_in,
                              void* d_out, int out_size) {
    const int*   t_ptr   = (const int*)  d_in[0];
    const float* x       = (const float*)d_in[1];
    const float* s       = (const float*)d_in[2];
    const float* rw      = (const float*)d_in[3];
    const float* lw      = (const float*)d_in[4];
    const float* lb      = (const float*)d_in[5];
    const float* elarger = (const float*)d_in[6];
    const float* tsv     = (const float*)d_in[7];
    float* out = (float*)d_out;

    priors_kernel<<<dim3(8, ADAPTERS, CAPS), 256>>>(t_ptr, x, rw);
    routing_kernel<<<dim3(BATCH, CAPS), 256>>>(t_ptr, tsv);
    gw_kernel<<<3, 256>>>(t_ptr, s, lw, lb, elarger);
    out_kernel<<<(BATCH * CLASS_DIM) / 8, 192>>>(out);
}

// round 10
// speedup vs baseline: 1.2574x; 1.2488x over previous
#include <cuda_runtime.h>
#include <cstdint>

#define ADAPTERS  40
#define CAPS      3
#define CLASS_DIM 200
#define IN_CH     600
#define BATCH     256
#define DOUT      768
#define PDIM      200                 // tight now (no wmma store constraints)

typedef unsigned long long ull;

// ---------------- scratch (device globals; no allocation allowed) ------------
__device__ float  g_priors[(size_t)CAPS * BATCH * ADAPTERS * PDIM]; // 24.6 MB
__device__ float  g_vote[(size_t)CAPS * BATCH * CLASS_DIM];
__device__ float4 g_gw[DOUT];

// Packed fp32x2 FMA (Blackwell FFMA2): d = a*b + d lane-wise on 2 floats.
#define FMA2(acc, a, b) \
    asm("fma.rn.f32x2 %0, %1, %2, %0;" : "+l"(acc) : "l"(a), "l"(b))

// ---------------- Stage A: priors[n,b,k,d] = sum_c x[b,k,c]*rw[k,n,c,d] -----
// fp32 GEMM on the FFMA2 pipe. Block tile 128(b) x 40(d), BK=24 (600 = 25*24),
// 160 threads (16 ty x 10 tx), microtile 8 rows x 4 cols (= 2 f32x2 pairs).
// A is stored DUPLICATED ({a,a}) in smem so no packing in the inner loop:
// per k-slice: 4 LDS.128 (A) + 1 LDS.128 (B) + 16 FFMA2.
#define BM  128
#define BN  40
#define BKC 24

__global__ __launch_bounds__(160) void priors_kernel(const int* __restrict__ t_ptr,
                                                     const float* __restrict__ x,
                                                     const float* __restrict__ rw) {
    const int k = blockIdx.y;
    const int n = blockIdx.z;
    if (k > *t_ptr) return;           // exactly-zero softmax weight downstream

    const int bt = blockIdx.x & 1;    // 2 b-tiles of 128
    const int dt = blockIdx.x >> 1;   // 5 d-tiles of 40 (200 exact, no waste)
    const int b0 = bt * BM;
    const int d0 = dt * BN;

    __shared__ float2 As2[BKC * BM];  // [cc][row] duplicated {a,a}; 24 KB
    __shared__ float  Bs[BKC * BN];   // [cc][dd];                   3.75 KB

    const int tid = threadIdx.x;      // 0..159
    const int tx  = tid % 10;         // d group (4 cols)
    const int ty  = tid / 10;         // 0..15 (8 rows)
    const int r0  = ty * 8;

    ull acc[16];                      // [u*2+p]: row u (0..7), pair p (0..1)
    #pragma unroll
    for (int i = 0; i < 16; i++) acc[i] = 0ull;

    const float* xk = x  + (size_t)k * IN_CH;
    const float* wk = rw + (size_t)(k * CAPS + n) * IN_CH * CLASS_DIM;

    for (int c0 = 0; c0 < IN_CH; c0 += BKC) {
        // ---- fill A (128 rows x 24 c), duplicated pairs ----
        for (int i = tid; i < BM * 6; i += 160) {
            int row = i / 6, c4 = (i % 6) * 4;
            float4 v = *(const float4*)&xk[(size_t)(b0 + row) * (ADAPTERS * IN_CH)
                                           + c0 + c4];
            As2[(c4 + 0) * BM + row] = make_float2(v.x, v.x);
            As2[(c4 + 1) * BM + row] = make_float2(v.y, v.y);
            As2[(c4 + 2) * BM + row] = make_float2(v.z, v.z);
            As2[(c4 + 3) * BM + row] = make_float2(v.w, v.w);
        }
        // ---- fill B (24 c x 40 d) ----
        for (int i = tid; i < BKC * 10; i += 160) {
            int cc = i / 10, d4 = (i % 10) * 4;
            float4 v = *(const float4*)&wk[(size_t)(c0 + cc) * CLASS_DIM + d0 + d4];
            *(float4*)&Bs[cc * BN + d4] = v;
        }
        __syncthreads();

        #pragma unroll
        for (int cc = 0; cc < BKC; cc++) {
            const ulonglong2* ap = (const ulonglong2*)(As2 + cc * BM + r0);
            ulonglong2 b = *(const ulonglong2*)(Bs + cc * BN + tx * 4);
            ulonglong2 a01 = ap[0], a23 = ap[1], a45 = ap[2], a67 = ap[3];
            FMA2(acc[ 0], a01.x, b.x); FMA2(acc[ 1], a01.x, b.y);
            FMA2(acc[ 2], a01.y, b.x); FMA2(acc[ 3], a01.y, b.y);
            FMA2(acc[ 4], a23.x, b.x); FMA2(acc[ 5], a23.x, b.y);
            FMA2(acc[ 6], a23.y, b.x); FMA2(acc[ 7], a23.y, b.y);
            FMA2(acc[ 8], a45.x, b.x); FMA2(acc[ 9], a45.x, b.y);
            FMA2(acc[10], a45.y, b.x); FMA2(acc[11], a45.y, b.y);
            FMA2(acc[12], a67.x, b.x); FMA2(acc[13], a67.x, b.y);
            FMA2(acc[14], a67.y, b.x); FMA2(acc[15], a67.y, b.y);
        }
        __syncthreads();
    }

    // ---- epilogue: each thread stores 8 rows x 1 float4 ----
    #pragma unroll
    for (int u = 0; u < 8; u++) {
        ull p0 = acc[u * 2], p1 = acc[u * 2 + 1];
        float4 o;
        o.x = __uint_as_float((unsigned)(p0 & 0xffffffffu));
        o.y = __uint_as_float((unsigned)(p0 >> 32));
        o.z = __uint_as_float((unsigned)(p1 & 0xffffffffu));
        o.w = __uint_as_float((unsigned)(p1 >> 32));
        *(float4*)&g_priors[(((size_t)n * BATCH + b0 + r0 + u) * ADAPTERS + k) * PDIM
                            + d0 + tx * 4] = o;
    }
}

// ---------------- Stage B: dynamic routing (3 iterations) --------------------
__global__ void routing_kernel(const int* __restrict__ t_ptr,
                               const float* __restrict__ tsv) {
    const int b   = blockIdx.x;
    const int n   = blockIdx.y;
    const int t   = *t_ptr;
    const int nk  = t + 1;
    const int tid = threadIdx.x;

    __shared__ float sp[ADAPTERS][CLASS_DIM]; // 32 KB
    __shared__ float sout[CLASS_DIM];
    __shared__ float sL[ADAPTERS];
    __shared__ float sprob[ADAPTERS];
    __shared__ float stw[ADAPTERS];
    __shared__ float red[256];

    const float* pbase = g_priors + (((size_t)n * BATCH + b) * ADAPTERS) * PDIM;
    for (int i = tid; i < nk * CLASS_DIM; i += 256)
        sp[i / CLASS_DIM][i % CLASS_DIM] = pbase[i];   // PDIM == CLASS_DIM: contiguous

    if (tid < ADAPTERS) {
        sL[tid]  = 0.f;
        stw[tid] = tsv[t * ADAPTERS + tid];
    }
    __syncthreads();

    for (int it = 0; it < 3; it++) {
        if (tid == 0) {
            float mx = -1e30f;
            for (int kk = 0; kk < nk; kk++) {
                float tw = stw[kk];
                float L  = sL[kk] * tw + (tw == 0.f ? -10000.f : 0.f);
                sL[kk] = L;
                mx = fmaxf(mx, L);
            }
            float s = 0.f;
            for (int kk = 0; kk < nk; kk++) {
                float e = expf(sL[kk] - mx);
                sprob[kk] = e;
                s += e;
            }
            float inv = 1.f / s;
            for (int kk = 0; kk < nk; kk++) sprob[kk] *= inv;
        }
        __syncthreads();

        float v = 0.f;
        if (tid < CLASS_DIM)
            for (int kk = 0; kk < nk; kk++) v += sprob[kk] * sp[kk][tid];

        red[tid] = (tid < CLASS_DIM) ? v * v : 0.f;
        __syncthreads();
        for (int s = 128; s > 0; s >>= 1) {
            if (tid < s) red[tid] += red[tid + s];
            __syncthreads();
        }
        float sq = red[0];

        if (it == 2) {
            if (tid < CLASS_DIM)
                g_vote[((size_t)n * BATCH + b) * CLASS_DIM + tid] = v;
        } else {
            float scale = sq / (1.f + sq) * rsqrtf(sq);
            if (tid < CLASS_DIM) sout[tid] = v * scale;
            __syncthreads();
            int wd = tid >> 5, lane = tid & 31;
            for (int kk = wd; kk < nk; kk += 8) {
                float p = 0.f;
                for (int d = lane; d < CLASS_DIM; d += 32) p += sp[kk][d] * sout[d];
                #pragma unroll
                for (int off = 16; off; off >>= 1)
                    p += __shfl_down_sync(0xffffffffu, p, off);
                if (lane == 0) sL[kk] += p;
            }
            __syncthreads();
        }
    }
}

// ---------------- Stage pre-C: fold gate into weights ------------------------
__global__ void gw_kernel(const int* __restrict__ t_ptr,
                          const float* __restrict__ s,
                          const float* __restrict__ lw,
                          const float* __restrict__ lb,
                          const float* __restrict__ elarger) {
    int j = blockIdx.x * 256 + threadIdx.x;
    if (j >= DOUT) return;
    int t = *t_ptr;
    float g = 1.f / (1.f + expf(-s[0] * elarger[t * DOUT + j]));
    float4 w;
    w.x = g * lw[j * 3 + 0];
    w.y = g * lw[j * 3 + 1];
    w.z = g * lw[j * 3 + 2];
    w.w = g * lb[j];
    g_gw[j] = w;
}

// ---------------- Stage C: out[row, j] = sum_c h_c * gw[j].c + gw[j].w -------
__global__ void out_kernel(float* __restrict__ out) {
    const int tid = threadIdx.x;       // 0..191
    float4 w[4];
    #pragma unroll
    for (int q = 0; q < 4; q++) w[q] = g_gw[tid * 4 + q];

    size_t row = (size_t)blockIdx.x * 8;
    #pragma unroll
    for (int r = 0; r < 8; r++, row++) {
        float v0 = g_vote[row * 3 + 0];
        float v1 = g_vote[row * 3 + 1];
        float v2 = g_vote[row * 3 + 2];
        float4 res;
        res.x = v0 * w[0].x + v1 * w[0].y + v2 * w[0].z + w[0].w;
        res.y = v0 * w[1].x + v1 * w[1].y + v2 * w[1].z + w[1].w;
        res.z = v0 * w[2].x + v1 * w[2].y + v2 * w[2].z + w[2].w;
        res.w = v0 * w[3].x + v1 * w[3].y + v2 * w[3].z + w[3].w;
        __stcs(((float4*)(out + row * DOUT)) + tid, res);
    }
}

// ---------------- launch -----------------------------------------------------
extern "C" void kernel_launch(void* const* d_in, const int* in_sizes, int n_in,
                              void* d_out, int out_size) {
    const int*   t_ptr   = (const int*)  d_in[0];
    const float* x       = (const float*)d_in[1];
    const float* s       = (const float*)d_in[2];
    const float* rw      = (const float*)d_in[3];
    const float* lw      = (const float*)d_in[4];
    const float* lb      = (const float*)d_in[5];
    const float* elarger = (const float*)d_in[6];
    const float* tsv     = (const float*)d_in[7];
    float* out = (float*)d_out;

    priors_kernel<<<dim3(10, ADAPTERS, CAPS), 160>>>(t_ptr, x, rw);
    routing_kernel<<<dim3(BATCH, CAPS), 256>>>(t_ptr, tsv);
    gw_kernel<<<3, 256>>>(t_ptr, s, lw, lb, elarger);
    out_kernel<<<(BATCH * CLASS_DIM) / 8, 192>>>(out);
}

// round 13
// speedup vs baseline: 1.5430x; 1.2272x over previous
#include <cuda_runtime.h>
#include <cstdint>

#define ADAPTERS  40
#define CAPS      3
#define CLASS_DIM 200
#define IN_CH     600
#define BATCH     256
#define DOUT      768
#define PDIM      200

typedef unsigned long long ull;

// ---------------- scratch (device globals; no allocation allowed) ------------
__device__ float  g_priors[(size_t)CAPS * BATCH * ADAPTERS * PDIM]; // 24.6 MB
__device__ float  g_vote[(size_t)CAPS * BATCH * CLASS_DIM];
__device__ float4 g_gw[DOUT];

// Packed fp32x2 FMA (Blackwell FFMA2): d = a*b + d lane-wise on 2 floats.
#define FMA2(acc, a, b) \
    asm("fma.rn.f32x2 %0, %1, %2, %0;" : "+l"(acc) : "l"(a), "l"(b))
// Duplicate one fp32 into both lanes of an f32x2 (ALU-pipe mov.b64).
#define DUP2(dst, f) \
    asm("mov.b64 %0, {%1, %1};" : "=l"(dst) : "r"(__float_as_uint(f)))

// ---------------- Stage A: priors[n,b,k,d] = sum_c x[b,k,c]*rw[k,n,c,d] -----
// FFMA2 GEMM, LDS-lean: per k-slice/thread 4 LDS.128 + 8 DUP + 32 FFMA2.
// Block tile 256(b) x 40(d), BK=24 (600=25*24), 160 threads (32 ty x 5 tx),
// microtile 8 rows x 8 cols; acc pairs packed along d -> B natural pairs,
// A duplicated in registers (ALU pipe), NOT in smem.
#define BM  256
#define BN  40
#define BKC 24

__global__ __launch_bounds__(160) void priors_kernel(const int* __restrict__ t_ptr,
                                                     const float* __restrict__ x,
                                                     const float* __restrict__ rw) {
    const int k = blockIdx.y;
    const int n = blockIdx.z;
    if (k > *t_ptr) return;           // exactly-zero softmax weight downstream

    const int d0 = blockIdx.x * BN;   // 5 d-tiles of 40 (exact)

    __shared__ float As[BKC * BM];    // [cc][row], 24.6 KB
    __shared__ float Bs[BKC * BN];    // [cc][dd],   3.75 KB

    const int tid = threadIdx.x;      // 0..159
    const int tx  = tid % 5;          // col group: 8 cols
    const int ty  = tid / 5;          // 0..31: 8 rows
    const int r0  = ty * 8;
    const int dc0 = tx * 8;

    ull acc[8][4];                    // [row][col-pair]
    #pragma unroll
    for (int r = 0; r < 8; r++)
        #pragma unroll
        for (int j = 0; j < 4; j++) acc[r][j] = 0ull;

    const float* xk = x  + (size_t)k * IN_CH;
    const float* wk = rw + (size_t)(k * CAPS + n) * IN_CH * CLASS_DIM;

    for (int c0 = 0; c0 < IN_CH; c0 += BKC) {
        // ---- fill A (256 rows x 24 c): thread->row mapping, STS conflict-free
        #pragma unroll
        for (int i = tid; i < BM * 6; i += 160) {
            int row = i & 255, c4 = (i >> 8) * 4;
            float4 v = *(const float4*)&xk[(size_t)row * (ADAPTERS * IN_CH) + c0 + c4];
            As[(c4 + 0) * BM + row] = v.x;
            As[(c4 + 1) * BM + row] = v.y;
            As[(c4 + 2) * BM + row] = v.z;
            As[(c4 + 3) * BM + row] = v.w;
        }
        // ---- fill B (24 c x 40 d) ----
        #pragma unroll
        for (int i = tid; i < BKC * 10; i += 160) {
            int cc = i / 10, d4 = (i % 10) * 4;
            *(float4*)&Bs[cc * BN + d4] =
                *(const float4*)&wk[(size_t)(c0 + cc) * CLASS_DIM + d0 + d4];
        }
        __syncthreads();

        #pragma unroll 4
        for (int cc = 0; cc < BKC; cc++) {
            float4 a0 = *(const float4*)&As[cc * BM + r0];
            float4 a1 = *(const float4*)&As[cc * BM + r0 + 4];
            ulonglong2 b01 = *(const ulonglong2*)&Bs[cc * BN + dc0];     // (d0,d1),(d2,d3)
            ulonglong2 b23 = *(const ulonglong2*)&Bs[cc * BN + dc0 + 4]; // (d4,d5),(d6,d7)
            ull ad[8];
            DUP2(ad[0], a0.x); DUP2(ad[1], a0.y); DUP2(ad[2], a0.z); DUP2(ad[3], a0.w);
            DUP2(ad[4], a1.x); DUP2(ad[5], a1.y); DUP2(ad[6], a1.z); DUP2(ad[7], a1.w);
            #pragma unroll
            for (int r = 0; r < 8; r++) {
                FMA2(acc[r][0], ad[r], b01.x);
                FMA2(acc[r][1], ad[r], b01.y);
                FMA2(acc[r][2], ad[r], b23.x);
                FMA2(acc[r][3], ad[r], b23.y);
            }
        }
        __syncthreads();
    }

    // ---- epilogue: per row, pairs are already d-ordered -> 2 float4 stores --
    #pragma unroll
    for (int r = 0; r < 8; r++) {
        float* dst = &g_priors[(((size_t)n * BATCH + r0 + r) * ADAPTERS + k) * PDIM
                               + d0 + dc0];
        float4 o0, o1;
        o0.x = __uint_as_float((unsigned)(acc[r][0] & 0xffffffffu));
        o0.y = __uint_as_float((unsigned)(acc[r][0] >> 32));
        o0.z = __uint_as_float((unsigned)(acc[r][1] & 0xffffffffu));
        o0.w = __uint_as_float((unsigned)(acc[r][1] >> 32));
        o1.x = __uint_as_float((unsigned)(acc[r][2] & 0xffffffffu));
        o1.y = __uint_as_float((unsigned)(acc[r][2] >> 32));
        o1.z = __uint_as_float((unsigned)(acc[r][3] & 0xffffffffu));
        o1.w = __uint_as_float((unsigned)(acc[r][3] >> 32));
        *(float4*)(dst)     = o0;
        *(float4*)(dst + 4) = o1;
    }
}

// ---------------- Stage B: dynamic routing (3 iterations) --------------------
__global__ void routing_kernel(const int* __restrict__ t_ptr,
                               const float* __restrict__ tsv) {
    const int b   = blockIdx.x;
    const int n   = blockIdx.y;
    const int t   = *t_ptr;
    const int nk  = t + 1;
    const int tid = threadIdx.x;

    __shared__ float sp[ADAPTERS][CLASS_DIM]; // 32 KB
    __shared__ float sout[CLASS_DIM];
    __shared__ float sL[ADAPTERS];
    __shared__ float sprob[ADAPTERS];
    __shared__ float stw[ADAPTERS];
    __shared__ float red[256];

    const float* pbase = g_priors + (((size_t)n * BATCH + b) * ADAPTERS) * PDIM;
    for (int i = tid; i < nk * CLASS_DIM; i += 256)
        sp[i / CLASS_DIM][i % CLASS_DIM] = pbase[i];   // PDIM == CLASS_DIM

    if (tid < ADAPTERS) {
        sL[tid]  = 0.f;
        stw[tid] = tsv[t * ADAPTERS + tid];
    }
    __syncthreads();

    for (int it = 0; it < 3; it++) {
        if (tid == 0) {
            float mx = -1e30f;
            for (int kk = 0; kk < nk; kk++) {
                float tw = stw[kk];
                float L  = sL[kk] * tw + (tw == 0.f ? -10000.f : 0.f);
                sL[kk] = L;
                mx = fmaxf(mx, L);
            }
            float s = 0.f;
            for (int kk = 0; kk < nk; kk++) {
                float e = expf(sL[kk] - mx);
                sprob[kk] = e;
                s += e;
            }
            float inv = 1.f / s;
            for (int kk = 0; kk < nk; kk++) sprob[kk] *= inv;
        }
        __syncthreads();

        float v = 0.f;
        if (tid < CLASS_DIM)
            for (int kk = 0; kk < nk; kk++) v += sprob[kk] * sp[kk][tid];

        red[tid] = (tid < CLASS_DIM) ? v * v : 0.f;
        __syncthreads();
        for (int s = 128; s > 0; s >>= 1) {
            if (tid < s) red[tid] += red[tid + s];
            __syncthreads();
        }
        float sq = red[0];

        if (it == 2) {
            if (tid < CLASS_DIM)
                g_vote[((size_t)n * BATCH + b) * CLASS_DIM + tid] = v;
        } else {
            float scale = sq / (1.f + sq) * rsqrtf(sq);
            if (tid < CLASS_DIM) sout[tid] = v * scale;
            __syncthreads();
            int wd = tid >> 5, lane = tid & 31;
            for (int kk = wd; kk < nk; kk += 8) {
                float p = 0.f;
                for (int d = lane; d < CLASS_DIM; d += 32) p += sp[kk][d] * sout[d];
                #pragma unroll
                for (int off = 16; off; off >>= 1)
                    p += __shfl_down_sync(0xffffffffu, p, off);
                if (lane == 0) sL[kk] += p;
            }
            __syncthreads();
        }
    }
}

// ---------------- Stage pre-C: fold gate into weights ------------------------
__global__ void gw_kernel(const int* __restrict__ t_ptr,
                          const float* __restrict__ s,
                          const float* __restrict__ lw,
                          const float* __restrict__ lb,
                          const float* __restrict__ elarger) {
    int j = blockIdx.x * 256 + threadIdx.x;
    if (j >= DOUT) return;
    int t = *t_ptr;
    float g = 1.f / (1.f + expf(-s[0] * elarger[t * DOUT + j]));
    float4 w;
    w.x = g * lw[j * 3 + 0];
    w.y = g * lw[j * 3 + 1];
    w.z = g * lw[j * 3 + 2];
    w.w = g * lb[j];
    g_gw[j] = w;
}

// ---------------- Stage C: out[row, j] = sum_c h_c * gw[j].c + gw[j].w -------
__global__ void out_kernel(float* __restrict__ out) {
    const int tid = threadIdx.x;       // 0..191
    float4 w[4];
    #pragma unroll
    for (int q = 0; q < 4; q++) w[q] = g_gw[tid * 4 + q];

    size_t row = (size_t)blockIdx.x * 8;
    #pragma unroll
    for (int r = 0; r < 8; r++, row++) {
        float v0 = g_vote[row * 3 + 0];
        float v1 = g_vote[row * 3 + 1];
        float v2 = g_vote[row * 3 + 2];
        float4 res;
        res.x = v0 * w[0].x + v1 * w[0].y + v2 * w[0].z + w[0].w;
        res.y = v0 * w[1].x + v1 * w[1].y + v2 * w[1].z + w[1].w;
        res.z = v0 * w[2].x + v1 * w[2].y + v2 * w[2].z + w[2].w;
        res.w = v0 * w[3].x + v1 * w[3].y + v2 * w[3].z + w[3].w;
        __stcs(((float4*)(out + row * DOUT)) + tid, res);
    }
}

// ---------------- launch -----------------------------------------------------
extern "C" void kernel_launch(void* const* d_in, const int* in_sizes, int n_in,
                              void* d_out, int out_size) {
    const int*   t_ptr   = (const int*)  d_in[0];
    const float* x       = (const float*)d_in[1];
    const float* s       = (const float*)d_in[2];
    const float* rw      = (const float*)d_in[3];
    const float* lw      = (const float*)d_in[4];
    const float* lb      = (const float*)d_in[5];
    const float* elarger = (const float*)d_in[6];
    const float* tsv     = (const float*)d_in[7];
    float* out = (float*)d_out;

    priors_kernel<<<dim3(5, ADAPTERS, CAPS), 160>>>(t_ptr, x, rw);
    routing_kernel<<<dim3(BATCH, CAPS), 256>>>(t_ptr, tsv);
    gw_kernel<<<3, 256>>>(t_ptr, s, lw, lb, elarger);
    out_kernel<<<(BATCH * CLASS_DIM) / 8, 192>>>(out);
}